// round 1
// baseline (speedup 1.0000x reference)
#include <cuda_runtime.h>
#include <math.h>
#include <float.h>

// ---------------- problem constants ----------------
#define S_LEN   65536
#define H_DIM   512
#define A_DIM   256
#define H2_DIM  1024

// score-GEMM tiling
#define BM 128          // rows of si per block
#define BK 16           // K chunk
// thread layout: 16 (tx, cols) x 16 (ty, rows); each thread: 8 rows x 16 cols

// context pass
#define CTX_ROWS 128    // rows per block
#define CTX_BLOCKS (S_LEN / CTX_ROWS)   // 512

// ---------------- scratch (no allocations allowed) ----------------
__device__ float g_waT[H_DIM * A_DIM];     // Wa transposed: [h][a]
__device__ float g_encp[A_DIM];            // enc_proj
__device__ float g_e[S_LEN];               // raw scores
__device__ float g_stats[2];               // {max, 1/sumexp}
__device__ float g_part[CTX_BLOCKS * H_DIM]; // per-block context partials

// ---------------- small helpers ----------------
__device__ __forceinline__ float warp_sum(float v) {
    #pragma unroll
    for (int o = 16; o > 0; o >>= 1) v += __shfl_xor_sync(0xFFFFFFFFu, v, o);
    return v;
}
__device__ __forceinline__ float warp_max(float v) {
    #pragma unroll
    for (int o = 16; o > 0; o >>= 1) v = fmaxf(v, __shfl_xor_sync(0xFFFFFFFFu, v, o));
    return v;
}

// ---------------- kernel 0: transpose Wa [A,H] -> waT [H,A] ----------------
__global__ void k_transpose_wa(const float* __restrict__ Wa) {
    int idx = blockIdx.x * 256 + threadIdx.x;
    if (idx < A_DIM * H_DIM) {
        int a = idx >> 9;          // / H_DIM
        int h = idx & (H_DIM - 1);
        g_waT[h * A_DIM + a] = Wa[idx];
    }
}

// ---------------- kernel 1: enc_proj[a] = sum_h enc_out[h] * Ua[a,h] -------
__global__ void k_encproj(const float* __restrict__ enc, const float* __restrict__ Ua) {
    int a = blockIdx.x;            // 256 blocks
    int tid = threadIdx.x;         // 256 threads
    float s = 0.f;
    #pragma unroll
    for (int j = 0; j < 4; j++) {
        int h = tid + j * 256;
        s += enc[h] * Ua[(size_t)a * H2_DIM + h];
    }
    __shared__ float red[8];
    s = warp_sum(s);
    int wid = tid >> 5, lane = tid & 31;
    if (lane == 0) red[wid] = s;
    __syncthreads();
    if (wid == 0) {
        float v = (lane < 8) ? red[lane] : 0.f;
        v = warp_sum(v);
        if (lane == 0) g_encp[a] = v;
    }
}

// ---------------- kernel 2: scores e[s] = va . tanh(si@WaT + encp) --------
// Register-blocked 128x256 fp32 GEMM fused with tanh + va reduction.
__global__ __launch_bounds__(256)
void k_scores(const float* __restrict__ si, const float* __restrict__ va) {
    __shared__ float s_si[BK][BM];        // transposed si tile   (8 KB)
    __shared__ float s_w[BK][A_DIM];      // waT tile             (16 KB)
    __shared__ float s_red[BM][17];       // row reduction        (8.7 KB)

    const int tid = threadIdx.x;
    const int tx = tid & 15;   // col group (16 cols per thread, strided)
    const int ty = tid >> 4;   // row group (8 rows per thread, strided)
    const int s0 = blockIdx.x * BM;

    float acc[8][16];
    #pragma unroll
    for (int i = 0; i < 8; i++)
        #pragma unroll
        for (int j = 0; j < 16; j++) acc[i][j] = 0.f;

    for (int k0 = 0; k0 < H_DIM; k0 += BK) {
        // load si tile (128 rows x 16 cols), store transposed [k][row]
        #pragma unroll
        for (int i = tid; i < 512; i += 256) {
            int r = i >> 2, kv = i & 3;
            float4 v = *(const float4*)(si + (size_t)(s0 + r) * H_DIM + k0 + kv * 4);
            s_si[kv * 4 + 0][r] = v.x;
            s_si[kv * 4 + 1][r] = v.y;
            s_si[kv * 4 + 2][r] = v.z;
            s_si[kv * 4 + 3][r] = v.w;
        }
        // load waT tile (16 rows x 256 cols)
        #pragma unroll
        for (int i = tid; i < 1024; i += 256) {
            int k = i >> 6, av = (i & 63) * 4;
            *(float4*)&s_w[k][av] = *(const float4*)(g_waT + (size_t)(k0 + k) * A_DIM + av);
        }
        __syncthreads();

        #pragma unroll
        for (int k = 0; k < BK; k++) {
            float a0[8], b0[16];
            // rows: ty*4 + i (i<4)  and  64 + ty*4 + i
            *(float4*)&a0[0] = *(float4*)&s_si[k][ty * 4];
            *(float4*)&a0[4] = *(float4*)&s_si[k][64 + ty * 4];
            // cols: c*64 + tx*4 + jj  (conflict-free 16B strided)
            #pragma unroll
            for (int c = 0; c < 4; c++)
                *(float4*)&b0[c * 4] = *(float4*)&s_w[k][c * 64 + tx * 4];
            #pragma unroll
            for (int i = 0; i < 8; i++)
                #pragma unroll
                for (int j = 0; j < 16; j++)
                    acc[i][j] = fmaf(a0[i], b0[j], acc[i][j]);
        }
        __syncthreads();
    }

    // epilogue: tanh(acc + encp[a]) * va[a], reduce over this thread's 16 cols
    float rowsum[8];
    #pragma unroll
    for (int i = 0; i < 8; i++) rowsum[i] = 0.f;
    #pragma unroll
    for (int j = 0; j < 16; j++) {
        int a = (j >> 2) * 64 + tx * 4 + (j & 3);
        float ep = g_encp[a];
        float vv = va[a];
        #pragma unroll
        for (int i = 0; i < 8; i++)
            rowsum[i] += tanhf(acc[i][j] + ep) * vv;
    }
    #pragma unroll
    for (int i = 0; i < 8; i++) {
        int row = (i < 4) ? (ty * 4 + i) : (64 + ty * 4 + (i - 4));
        s_red[row][tx] = rowsum[i];
    }
    __syncthreads();
    if (tid < BM) {
        float s = 0.f;
        #pragma unroll
        for (int j = 0; j < 16; j++) s += s_red[tid][j];
        g_e[s0 + tid] = s;
    }
}

// ---------------- kernel 3: softmax stats (max, 1/sumexp) -----------------
__global__ void k_stats() {
    __shared__ float red[32];
    __shared__ float s_m;
    const int tid = threadIdx.x;   // 1024 threads, 1 block
    const int wid = tid >> 5, lane = tid & 31;

    float mx = -FLT_MAX;
    for (int i = tid; i < S_LEN; i += 1024) mx = fmaxf(mx, g_e[i]);
    mx = warp_max(mx);
    if (lane == 0) red[wid] = mx;
    __syncthreads();
    if (wid == 0) {
        float v = (lane < 32) ? red[lane] : -FLT_MAX;
        v = warp_max(v);
        if (lane == 0) s_m = v;
    }
    __syncthreads();
    const float m = s_m;

    float sum = 0.f;
    for (int i = tid; i < S_LEN; i += 1024) sum += expf(g_e[i] - m);
    sum = warp_sum(sum);
    if (lane == 0) red[wid] = sum;
    __syncthreads();
    if (wid == 0) {
        float v = (lane < 32) ? red[lane] : 0.f;
        v = warp_sum(v);
        if (lane == 0) { g_stats[0] = m; g_stats[1] = 1.f / v; }
    }
}

// ---------------- kernel 4: alpha out + context partials ------------------
__global__ void k_context(const float* __restrict__ si, float* __restrict__ out) {
    __shared__ float s_wt[CTX_ROWS];
    const int b = blockIdx.x;            // 512 blocks
    const int tid = threadIdx.x;         // 256 threads
    const float m = g_stats[0];
    const float inv_l = g_stats[1];
    const int srow = b * CTX_ROWS;

    if (tid < CTX_ROWS) {
        float w = expf(g_e[srow + tid] - m) * inv_l;
        s_wt[tid] = w;
        out[H_DIM + srow + tid] = w;     // alpha output
    }
    __syncthreads();

    float c0 = 0.f, c1 = 0.f;
    for (int r = 0; r < CTX_ROWS; r++) {
        float w = s_wt[r];
        float2 v = *(const float2*)(si + (size_t)(srow + r) * H_DIM + tid * 2);
        c0 = fmaf(w, v.x, c0);
        c1 = fmaf(w, v.y, c1);
    }
    g_part[(size_t)b * H_DIM + tid * 2 + 0] = c0;
    g_part[(size_t)b * H_DIM + tid * 2 + 1] = c1;
}

// ---------------- kernel 5: reduce context partials -----------------------
__global__ void k_ctx_reduce(float* __restrict__ out) {
    const int h = threadIdx.x;           // 512 threads, 1 block
    float s = 0.f;
    for (int b = 0; b < CTX_BLOCKS; b++)
        s += g_part[(size_t)b * H_DIM + h];
    out[h] = s;
}

// ---------------- launch ---------------------------------------------------
extern "C" void kernel_launch(void* const* d_in, const int* in_sizes, int n_in,
                              void* d_out, int out_size) {
    const float* enc = (const float*)d_in[0];   // [1024]
    const float* si  = (const float*)d_in[1];   // [65536*512]
    const float* Wa  = (const float*)d_in[2];   // [256*512]
    const float* Ua  = (const float*)d_in[3];   // [256*1024]
    const float* va  = (const float*)d_in[4];   // [256]
    float* out = (float*)d_out;                 // [512 context | 65536 alpha]

    k_transpose_wa<<<(A_DIM * H_DIM + 255) / 256, 256>>>(Wa);
    k_encproj<<<A_DIM, 256>>>(enc, Ua);
    k_scores<<<S_LEN / BM, 256>>>(si, va);
    k_stats<<<1, 1024>>>();
    k_context<<<CTX_BLOCKS, 256>>>(si, out);
    k_ctx_reduce<<<1, H_DIM>>>(out);
}

// round 4
// speedup vs baseline: 2.6810x; 2.6810x over previous
#include <cuda_runtime.h>
#include <math.h>
#include <float.h>
#include <stdint.h>

// ---------------- problem constants ----------------
#define S_LEN   65536
#define H_DIM   512
#define A_DIM   256
#define H2_DIM  1024

#define TILE_M     128
#define NUM_TILES  (S_LEN / TILE_M)    // 512
#define BK         32
#define NIT        (H_DIM / BK)        // 16

// smem tile strides (floats). 36 = 32 + 4 pad -> conflict-free frag loads
#define SA 36
#define A_TILE_F  (128 * SA)           // 4608 floats = 18432 B
#define B_TILE_F  (256 * SA)           // 9216 floats = 36864 B
#define BUF_F     (A_TILE_F + B_TILE_F)        // 13824 floats = 55296 B
#define EPI_F     (2 * BUF_F)                  // epilogue region offset (floats)
#define SMEM_BYTES (2 * BUF_F * 4 + (256 + 256 + 128 * 5) * 4 + 256)

// context pass
#define CTX_ROWS 128
#define CTX_BLOCKS (S_LEN / CTX_ROWS)  // 512

// ---------------- scratch ----------------
__device__ float g_encp[A_DIM];
__device__ float g_e[S_LEN];
__device__ float g_bm[NUM_TILES];
__device__ float g_bl[NUM_TILES];
__device__ float g_stats[2];                   // {M, 1/L}
__device__ float g_part[CTX_BLOCKS * H_DIM];

// ---------------- helpers ----------------
__device__ __forceinline__ float warp_sum(float v) {
    #pragma unroll
    for (int o = 16; o > 0; o >>= 1) v += __shfl_xor_sync(0xFFFFFFFFu, v, o);
    return v;
}
__device__ __forceinline__ float warp_max(float v) {
    #pragma unroll
    for (int o = 16; o > 0; o >>= 1) v = fmaxf(v, __shfl_xor_sync(0xFFFFFFFFu, v, o));
    return v;
}
__device__ __forceinline__ uint32_t smem_u32(const void* p) {
    uint32_t a;
    asm("{ .reg .u64 t; cvta.to.shared.u64 t, %1; cvt.u32.u64 %0, t; }" : "=r"(a) : "l"(p));
    return a;
}
__device__ __forceinline__ void cp_async16(uint32_t dst, const void* src) {
    asm volatile("cp.async.cg.shared.global [%0], [%1], 16;" :: "r"(dst), "l"(src));
}
__device__ __forceinline__ uint32_t f2tf32(float f) {
    uint32_t u;
    asm("cvt.rna.tf32.f32 %0, %1;" : "=r"(u) : "f"(f));
    return u;
}
__device__ __forceinline__ void mma_tf32(float c[4], uint32_t a0, uint32_t a1,
                                         uint32_t a2, uint32_t a3,
                                         uint32_t b0, uint32_t b1) {
    asm volatile(
        "mma.sync.aligned.m16n8k8.row.col.f32.tf32.tf32.f32 "
        "{%0,%1,%2,%3}, {%4,%5,%6,%7}, {%8,%9}, {%0,%1,%2,%3};"
        : "+f"(c[0]), "+f"(c[1]), "+f"(c[2]), "+f"(c[3])
        : "r"(a0), "r"(a1), "r"(a2), "r"(a3), "r"(b0), "r"(b1));
}

// ---------------- kernel 1: enc_proj ----------------
__global__ void k_encproj(const float* __restrict__ enc, const float* __restrict__ Ua) {
    int a = blockIdx.x;
    int tid = threadIdx.x;
    float s = 0.f;
    #pragma unroll
    for (int j = 0; j < 4; j++) {
        int h = tid + j * 256;
        s += enc[h] * Ua[(size_t)a * H2_DIM + h];
    }
    __shared__ float red[8];
    s = warp_sum(s);
    int wid = tid >> 5, lane = tid & 31;
    if (lane == 0) red[wid] = s;
    __syncthreads();
    if (wid == 0) {
        float v = (lane < 8) ? red[lane] : 0.f;
        v = warp_sum(v);
        if (lane == 0) g_encp[a] = v;
    }
}

// ---------------- kernel 2: tf32 mma.sync score GEMM + fused epilogue -----
// Per block: D[128,256] = si_tile[128,512] @ Wa^T; e = tanh(D+encp)·va;
// writes g_e and per-block softmax partials.
__global__ __launch_bounds__(256, 1)
void k_scores_mma(const float* __restrict__ si, const float* __restrict__ Wa,
                  const float* __restrict__ va) {
    extern __shared__ __align__(16) float smem[];
    float* s_encp = smem + EPI_F;          // 256
    float* s_va   = s_encp + 256;          // 256
    float* s_red  = s_va + 256;            // 128 x 5

    const int tid  = threadIdx.x;
    const int lane = tid & 31;
    const int wid  = tid >> 5;
    const int wm   = wid & 1;              // 2 warps in M
    const int wn   = wid >> 1;             // 4 warps in N
    const int s0   = blockIdx.x * TILE_M;
    const int lg   = lane >> 2;            // group id 0..7
    const int lt   = lane & 3;             // thread-in-group 0..3

    s_encp[tid] = g_encp[tid];
    s_va[tid]   = va[tid];

    float acc[4][8][4];
    #pragma unroll
    for (int m = 0; m < 4; m++)
        #pragma unroll
        for (int n = 0; n < 8; n++)
            #pragma unroll
            for (int j = 0; j < 4; j++) acc[m][n][j] = 0.f;

    // -------- pipelined tile loads --------
    auto load_tile = [&](int buf, int k0) {
        uint32_t sa = smem_u32(smem + buf * BUF_F);
        uint32_t sbB = sa + A_TILE_F * 4;
        #pragma unroll
        for (int t = 0; t < 4; t++) {          // A: 1024 x 16B chunks
            int i = tid + t * 256;
            int r = i >> 3, c4 = i & 7;
            cp_async16(sa + r * (SA * 4) + c4 * 16,
                       si + (size_t)(s0 + r) * H_DIM + k0 + c4 * 4);
        }
        #pragma unroll
        for (int t = 0; t < 8; t++) {          // B: 2048 x 16B chunks
            int i = tid + t * 256;
            int r = i >> 3, c4 = i & 7;
            cp_async16(sbB + r * (SA * 4) + c4 * 16,
                       Wa + (size_t)r * H_DIM + k0 + c4 * 4);
        }
        asm volatile("cp.async.commit_group;" ::: "memory");
    };

    load_tile(0, 0);
    for (int c = 0; c < NIT; c++) {
        if (c + 1 < NIT) {
            load_tile((c + 1) & 1, (c + 1) * BK);
            asm volatile("cp.async.wait_group 1;" ::: "memory");
        } else {
            asm volatile("cp.async.wait_group 0;" ::: "memory");
        }
        __syncthreads();

        const float* sa = smem + (c & 1) * BUF_F;
        const float* sb = sa + A_TILE_F;

        #pragma unroll
        for (int ks = 0; ks < 4; ks++) {
            const int kk = ks * 8;
            uint32_t af[4][4], bf[8][2];
            #pragma unroll
            for (int m = 0; m < 4; m++) {
                int r0 = wm * 64 + m * 16 + lg;
                int c0 = kk + lt;
                af[m][0] = f2tf32(sa[r0 * SA + c0]);
                af[m][1] = f2tf32(sa[(r0 + 8) * SA + c0]);
                af[m][2] = f2tf32(sa[r0 * SA + c0 + 4]);
                af[m][3] = f2tf32(sa[(r0 + 8) * SA + c0 + 4]);
            }
            #pragma unroll
            for (int n = 0; n < 8; n++) {
                int nr = wn * 64 + n * 8 + lg;
                int kc = kk + lt;
                bf[n][0] = f2tf32(sb[nr * SA + kc]);
                bf[n][1] = f2tf32(sb[nr * SA + kc + 4]);
            }
            #pragma unroll
            for (int m = 0; m < 4; m++)
                #pragma unroll
                for (int n = 0; n < 8; n++)
                    mma_tf32(acc[m][n], af[m][0], af[m][1], af[m][2], af[m][3],
                             bf[n][0], bf[n][1]);
        }
        __syncthreads();
    }

    // -------- epilogue: e = sum_a tanh(acc + encp)·va, per row --------
    float rowsum[4][2];
    #pragma unroll
    for (int m = 0; m < 4; m++) { rowsum[m][0] = 0.f; rowsum[m][1] = 0.f; }

    #pragma unroll
    for (int n = 0; n < 8; n++) {
        int cb = wn * 64 + n * 8 + lt * 2;
        float e0 = s_encp[cb],     v0 = s_va[cb];
        float e1 = s_encp[cb + 1], v1 = s_va[cb + 1];
        #pragma unroll
        for (int m = 0; m < 4; m++) {
            rowsum[m][0] += tanhf(acc[m][n][0] + e0) * v0
                          + tanhf(acc[m][n][1] + e1) * v1;
            rowsum[m][1] += tanhf(acc[m][n][2] + e0) * v0
                          + tanhf(acc[m][n][3] + e1) * v1;
        }
    }
    // reduce across the 4 threads sharing each row (lane&3 group)
    #pragma unroll
    for (int m = 0; m < 4; m++)
        #pragma unroll
        for (int h = 0; h < 2; h++) {
            rowsum[m][h] += __shfl_xor_sync(0xFFFFFFFFu, rowsum[m][h], 1);
            rowsum[m][h] += __shfl_xor_sync(0xFFFFFFFFu, rowsum[m][h], 2);
        }
    if (lt == 0) {
        #pragma unroll
        for (int m = 0; m < 4; m++)
            #pragma unroll
            for (int h = 0; h < 2; h++) {
                int row = wm * 64 + m * 16 + lg + h * 8;
                s_red[row * 5 + wn] = rowsum[m][h];
            }
    }
    __syncthreads();

    float e_val = -FLT_MAX;
    if (tid < 128) {
        e_val = s_red[tid * 5 + 0] + s_red[tid * 5 + 1]
              + s_red[tid * 5 + 2] + s_red[tid * 5 + 3];
        g_e[s0 + tid] = e_val;
    }

    // block softmax partials over the 128 rows (warps 0-3 hold them)
    __shared__ float s_p[8];
    float mw = warp_max((tid < 128) ? e_val : -FLT_MAX);
    if (lane == 0) s_p[wid] = mw;
    __syncthreads();
    float m_b = fmaxf(fmaxf(s_p[0], s_p[1]), fmaxf(s_p[2], s_p[3]));
    float lw = warp_sum((tid < 128) ? expf(e_val - m_b) : 0.f);
    __syncthreads();
    if (lane == 0) s_p[wid] = lw;
    __syncthreads();
    if (tid == 0) {
        g_bm[blockIdx.x] = m_b;
        g_bl[blockIdx.x] = s_p[0] + s_p[1] + s_p[2] + s_p[3];
    }
}

// ---------------- kernel 3: combine per-block softmax partials ------------
__global__ void k_combine() {
    __shared__ float red[16];
    __shared__ float s_M;
    const int tid = threadIdx.x;          // 512 threads
    const int wid = tid >> 5, lane = tid & 31;

    float m = g_bm[tid];
    float wmv = warp_max(m);
    if (lane == 0) red[wid] = wmv;
    __syncthreads();
    if (tid == 0) {
        float M = -FLT_MAX;
        #pragma unroll
        for (int i = 0; i < 16; i++) M = fmaxf(M, red[i]);
        s_M = M;
    }
    __syncthreads();
    const float M = s_M;

    float l = g_bl[tid] * expf(g_bm[tid] - M);
    float wl = warp_sum(l);
    __syncthreads();
    if (lane == 0) red[wid] = wl;
    __syncthreads();
    if (tid == 0) {
        float L = 0.f;
        #pragma unroll
        for (int i = 0; i < 16; i++) L += red[i];
        g_stats[0] = M;
        g_stats[1] = 1.f / L;
    }
}

// ---------------- kernel 4: alpha out + context partials ------------------
__global__ void k_context(const float* __restrict__ si, float* __restrict__ out) {
    __shared__ float s_wt[CTX_ROWS];
    const int b = blockIdx.x;
    const int tid = threadIdx.x;          // 256
    const float m = g_stats[0];
    const float inv_l = g_stats[1];
    const int srow = b * CTX_ROWS;

    if (tid < CTX_ROWS) {
        float w = expf(g_e[srow + tid] - m) * inv_l;
        s_wt[tid] = w;
        out[H_DIM + srow + tid] = w;
    }
    __syncthreads();

    float c0 = 0.f, c1 = 0.f;
    for (int r = 0; r < CTX_ROWS; r++) {
        float w = s_wt[r];
        float2 v = *(const float2*)(si + (size_t)(srow + r) * H_DIM + tid * 2);
        c0 = fmaf(w, v.x, c0);
        c1 = fmaf(w, v.y, c1);
    }
    g_part[(size_t)b * H_DIM + tid * 2 + 0] = c0;
    g_part[(size_t)b * H_DIM + tid * 2 + 1] = c1;
}

// ---------------- kernel 5: reduce context partials -----------------------
__global__ void k_ctx_reduce(float* __restrict__ out) {
    const int h = threadIdx.x;
    float s = 0.f;
    for (int b = 0; b < CTX_BLOCKS; b++)
        s += g_part[(size_t)b * H_DIM + h];
    out[h] = s;
}

// ---------------- launch ---------------------------------------------------
extern "C" void kernel_launch(void* const* d_in, const int* in_sizes, int n_in,
                              void* d_out, int out_size) {
    const float* enc = (const float*)d_in[0];
    const float* si  = (const float*)d_in[1];
    const float* Wa  = (const float*)d_in[2];
    const float* Ua  = (const float*)d_in[3];
    const float* va  = (const float*)d_in[4];
    float* out = (float*)d_out;

    cudaFuncSetAttribute(k_scores_mma,
                         cudaFuncAttributeMaxDynamicSharedMemorySize, SMEM_BYTES);

    k_encproj<<<A_DIM, 256>>>(enc, Ua);
    k_scores_mma<<<NUM_TILES, 256, SMEM_BYTES>>>(si, Wa, va);
    k_combine<<<1, 512>>>();
    k_context<<<CTX_BLOCKS, 256>>>(si, out);
    k_ctx_reduce<<<1, H_DIM>>>(out);
}